// round 10
// baseline (speedup 1.0000x reference)
#include <cuda_runtime.h>
#include <stdint.h>
#include <math_constants.h>

// BoxLoss: elementwise CIoU + masked reduction, fused single kernel with a
// cp.async double-buffered box pipeline (barrier-free: each thread writes and
// reads only its own smem slot, so wait_group alone orders it).
//   0: predicts_bbox [B,A,4] f32
//   1: targets_bbox  [B,A,4] f32
//   2: valid_masks   [B,A]   bool/f32/i32 (dtype sniffed per-block)
//   3: box_norm      [B,A]   f32
//   4: cls_norm      []      f32
// Output: d_out[0] = loss_iou, d_out[1..N] = masked iou.

#define NBLOCKS  1184
#define NTHREADS 256
#define CHUNK    NTHREADS

__device__ float        g_partials[NBLOCKS];
__device__ unsigned int g_ticket = 0;

// ---------------- cp.async helpers ----------------
__device__ __forceinline__ uint32_t smem_u32(const void* p) {
    return (uint32_t)__cvta_generic_to_shared(p);
}
__device__ __forceinline__ void cp_async16(uint32_t dst, const void* src) {
    asm volatile("cp.async.cg.shared.global [%0], [%1], 16;"
                 :: "r"(dst), "l"(src));
}
__device__ __forceinline__ void cp_commit() {
    asm volatile("cp.async.commit_group;");
}
template <int N>
__device__ __forceinline__ void cp_wait() {
    asm volatile("cp.async.wait_group %0;" :: "n"(N));
}

// ---------------- mask dtype sniff ----------------
__device__ __forceinline__ int sniff_mask_mode(const uint32_t* mask_words) {
    uint32_t w = mask_words[threadIdx.x];          // first 1024 bytes
    int f32flag = 0, u8flag = 0;
    #pragma unroll
    for (int b = 0; b < 4; b++) {
        uint32_t byte = (w >> (8 * b)) & 0xFFu;
        if (byte == 0x3Fu || byte == 0x80u) f32flag = 1;
        if (byte == 0x01u && b != 0)        u8flag  = 1;
    }
    unsigned any_f32 = __ballot_sync(0xFFFFFFFFu, f32flag);
    unsigned any_u8  = __ballot_sync(0xFFFFFFFFu, u8flag);

    __shared__ int s_f32, s_u8, s_mode;
    if (threadIdx.x == 0) { s_f32 = 0; s_u8 = 0; }
    __syncthreads();
    if ((threadIdx.x & 31) == 0) {
        if (any_f32) atomicOr(&s_f32, 1);
        if (any_u8)  atomicOr(&s_u8, 1);
    }
    __syncthreads();
    if (threadIdx.x == 0) s_mode = s_f32 ? 0 : (s_u8 ? 1 : 2);
    __syncthreads();
    return s_mode;
}

__device__ __forceinline__ float block_reduce_sum(float v) {
    __shared__ float s_warp[NTHREADS / 32];
    #pragma unroll
    for (int off = 16; off > 0; off >>= 1)
        v += __shfl_down_sync(0xFFFFFFFFu, v, off);
    int lane = threadIdx.x & 31;
    int wid  = threadIdx.x >> 5;
    if (lane == 0) s_warp[wid] = v;
    __syncthreads();
    float r = 0.0f;
    if (threadIdx.x == 0) {
        #pragma unroll
        for (int w = 0; w < NTHREADS / 32; w++) r += s_warp[w];
    }
    return r;  // valid in thread 0 only
}

// branchless minimax atan, full range, max err ~1e-6
__device__ __forceinline__ float fast_atan(float t) {
    float at  = fabsf(t);
    bool  inv = at > 1.0f;
    float z   = inv ? __fdividef(1.0f, at) : at;   // z in [0,1]
    float z2  = z * z;
    float p   =              -0.0117212f;
    p = fmaf(p, z2,  0.05265332f);
    p = fmaf(p, z2, -0.11643287f);
    p = fmaf(p, z2,  0.19354346f);
    p = fmaf(p, z2, -0.33262347f);
    p = fmaf(p, z2,  0.99997726f);
    p *= z;
    float r = inv ? (CUDART_PIO2_F - p) : p;
    return copysignf(r, t);
}

// one element of masked CIoU; returns masked iou, accumulates loss term
__device__ __forceinline__ float ciou_elem(float4 a, float4 b, float m,
                                           float bn, float& acc) {
    const float EPS   = 1e-9f;
    const float C4PI2 = 4.0f / (CUDART_PI_F * CUDART_PI_F);

    float iw = fmaxf(fminf(a.z, b.z) - fmaxf(a.x, b.x), 0.0f);
    float ih = fmaxf(fminf(a.w, b.w) - fmaxf(a.y, b.y), 0.0f);
    float inter  = iw * ih;
    float wa = a.z - a.x, ha = a.w - a.y;
    float wb = b.z - b.x, hb = b.w - b.y;
    float uni = wa * ha + wb * hb - inter;
    float iou = __fdividef(inter, uni + EPS);

    float cw = fmaxf(a.z, b.z) - fminf(a.x, b.x);
    float ch = fmaxf(a.w, b.w) - fminf(a.y, b.y);
    float c2 = cw * cw + ch * ch + EPS;

    float dx   = (b.x + b.z - a.x - a.z) * 0.5f;
    float dy   = (b.y + b.w - a.y - a.w) * 0.5f;
    float rho2 = dx * dx + dy * dy;

    // atan(wb/(hb+e)) - atan(wa/(ha+e)) == atan(t), single division:
    float hae = ha + EPS, hbe = hb + EPS;
    float t_num = wb * hae - wa * hbe;
    float t_den = fmaf(hbe, hae, wa * wb);
    float t = __fdividef(t_num, t_den);
    float d = fast_atan(t);
    float v = C4PI2 * d * d;
    float av = __fdividef(v * v, 1.0f - iou + v + EPS);   // alpha * v

    float ciou_m = (iou - __fdividef(rho2, c2) - av) * m;
    acc += (1.0f - ciou_m) * bn * m;
    return ciou_m;
}

template <int MODE>
__device__ __forceinline__ float load_mask1(const void* mask, int i) {
    if (MODE == 0)      return ((const float*)mask)[i];
    else if (MODE == 1) return ((const uint8_t*)mask)[i] ? 1.0f : 0.0f;
    else                return ((const int*)mask)[i] ? 1.0f : 0.0f;
}

template <int MODE>
__device__ __forceinline__ float mainloop(const float4* __restrict__ pb,
                                          const float4* __restrict__ tb,
                                          const void*   __restrict__ mask,
                                          const float*  __restrict__ box_norm,
                                          float*        __restrict__ iou_out,
                                          int n,
                                          float4* s_pb, float4* s_tb) {
    float acc = 0.0f;
    const int tid     = threadIdx.x;
    const int nchunks = (n + CHUNK - 1) / CHUNK;
    const int cstride = gridDim.x;

    int chunk = blockIdx.x;
    if (chunk >= nchunks) return acc;

    // ---- prologue: prefetch chunk -> buffer 0, scalars -> registers ----
    int   i0 = chunk * CHUNK + tid;
    float bn_cur = 0.f, m_cur = 0.f;
    if (i0 < n) {
        cp_async16(smem_u32(&s_pb[tid]), &pb[i0]);
        cp_async16(smem_u32(&s_tb[tid]), &tb[i0]);
        bn_cur = box_norm[i0];
        m_cur  = load_mask1<MODE>(mask, i0);
    }
    cp_commit();

    int bufi = 0;
    while (chunk < nchunks) {
        int   nextc = chunk + cstride;
        float bn_next = 0.f, m_next = 0.f;

        if (nextc < nchunks) {
            // issue next chunk's box copies into the other buffer
            int j = nextc * CHUNK + tid;
            int nb = (bufi ^ 1) * CHUNK;
            if (j < n) {
                cp_async16(smem_u32(&s_pb[nb + tid]), &pb[j]);
                cp_async16(smem_u32(&s_tb[nb + tid]), &tb[j]);
                bn_next = box_norm[j];
                m_next  = load_mask1<MODE>(mask, j);
            }
            cp_commit();
            cp_wait<1>();   // current chunk's copies complete
        } else {
            cp_wait<0>();
        }

        // compute current chunk: thread reads ONLY its own smem slot
        int i = chunk * CHUNK + tid;
        if (i < n) {
            float4 a = s_pb[bufi * CHUNK + tid];
            float4 b = s_tb[bufi * CHUNK + tid];
            iou_out[i] = ciou_elem(a, b, m_cur, bn_cur, acc);
        }

        bn_cur = bn_next;
        m_cur  = m_next;
        bufi  ^= 1;
        chunk  = nextc;
    }
    return acc;
}

__global__ void __launch_bounds__(NTHREADS)
ciou_fused_kernel(const float4* __restrict__ pb,
                  const float4* __restrict__ tb,
                  const void*   __restrict__ mask,
                  const float*  __restrict__ box_norm,
                  const float*  __restrict__ cls_norm,
                  float*        __restrict__ out,
                  int n) {
    __shared__ float4 s_pb[2 * CHUNK];   // 8 KB
    __shared__ float4 s_tb[2 * CHUNK];   // 8 KB

    const int mode = sniff_mask_mode((const uint32_t*)mask);
    float* __restrict__ iou_out = out + 1;

    float acc;
    if (mode == 0)      acc = mainloop<0>(pb, tb, mask, box_norm, iou_out, n, s_pb, s_tb);
    else if (mode == 1) acc = mainloop<1>(pb, tb, mask, box_norm, iou_out, n, s_pb, s_tb);
    else                acc = mainloop<2>(pb, tb, mask, box_norm, iou_out, n, s_pb, s_tb);

    float bsum = block_reduce_sum(acc);

    __shared__ int s_is_last;
    if (threadIdx.x == 0) {
        g_partials[blockIdx.x] = bsum;
        __threadfence();
        unsigned prev = atomicAdd(&g_ticket, 1u);
        s_is_last = (prev == (unsigned)(gridDim.x - 1));
    }
    __syncthreads();

    if (s_is_last) {
        float v = 0.0f;
        for (int i = threadIdx.x; i < NBLOCKS; i += NTHREADS)
            v += g_partials[i];
        float total = block_reduce_sum(v);
        if (threadIdx.x == 0) {
            out[0] = total / cls_norm[0];
            g_ticket = 0;
        }
    }
}

extern "C" void kernel_launch(void* const* d_in, const int* in_sizes, int n_in,
                              void* d_out, int out_size) {
    const float4*  pb       = (const float4*)d_in[0];
    const float4*  tb       = (const float4*)d_in[1];
    const void*    mask     = d_in[2];
    const float*   box_norm = (const float*)d_in[3];
    const float*   cls_norm = (const float*)d_in[4];
    float*         out      = (float*)d_out;

    int n = in_sizes[2];

    ciou_fused_kernel<<<NBLOCKS, NTHREADS>>>(pb, tb, mask, box_norm,
                                             cls_norm, out, n);
}

// round 11
// speedup vs baseline: 1.2424x; 1.2424x over previous
#include <cuda_runtime.h>
#include <stdint.h>
#include <math_constants.h>

// BoxLoss: elementwise CIoU + masked reduction, fused single kernel.
// Dense layout indexed by OUTPUT position j (out[j] 128B-aligned per warp);
// inputs read at e = j-1.
//   0: predicts_bbox [B,A,4] f32
//   1: targets_bbox  [B,A,4] f32
//   2: valid_masks   [B,A]   bool/f32/i32 (dtype sniffed per-block)
//   3: box_norm      [B,A]   f32
//   4: cls_norm      []      f32
// Output: d_out[0] = loss_iou, d_out[1..N] = masked iou.

#define NBLOCKS  592          // 148 SMs * 4 CTAs of 512 threads
#define NTHREADS 512

__device__ float        g_partials[NBLOCKS];
__device__ unsigned int g_ticket = 0;

__device__ __forceinline__ int sniff_mask_mode(const uint32_t* mask_words) {
    uint32_t w = mask_words[threadIdx.x & 255];    // first 1024 bytes
    int f32flag = 0, u8flag = 0;
    #pragma unroll
    for (int b = 0; b < 4; b++) {
        uint32_t byte = (w >> (8 * b)) & 0xFFu;
        if (byte == 0x3Fu || byte == 0x80u) f32flag = 1;
        if (byte == 0x01u && b != 0)        u8flag  = 1;
    }
    unsigned any_f32 = __ballot_sync(0xFFFFFFFFu, f32flag);
    unsigned any_u8  = __ballot_sync(0xFFFFFFFFu, u8flag);

    __shared__ int s_f32, s_u8, s_mode;
    if (threadIdx.x == 0) { s_f32 = 0; s_u8 = 0; }
    __syncthreads();
    if ((threadIdx.x & 31) == 0) {
        if (any_f32) atomicOr(&s_f32, 1);
        if (any_u8)  atomicOr(&s_u8, 1);
    }
    __syncthreads();
    if (threadIdx.x == 0) s_mode = s_f32 ? 0 : (s_u8 ? 1 : 2);
    __syncthreads();
    return s_mode;
}

__device__ __forceinline__ float block_reduce_sum(float v) {
    __shared__ float s_warp[NTHREADS / 32];
    #pragma unroll
    for (int off = 16; off > 0; off >>= 1)
        v += __shfl_down_sync(0xFFFFFFFFu, v, off);
    int lane = threadIdx.x & 31;
    int wid  = threadIdx.x >> 5;
    if (lane == 0) s_warp[wid] = v;
    __syncthreads();
    float r = 0.0f;
    if (threadIdx.x == 0) {
        #pragma unroll
        for (int w = 0; w < NTHREADS / 32; w++) r += s_warp[w];
    }
    return r;  // valid in thread 0 only
}

// branchless minimax atan, full range, max err ~1e-6
__device__ __forceinline__ float fast_atan(float t) {
    float at  = fabsf(t);
    bool  inv = at > 1.0f;
    float z   = inv ? __fdividef(1.0f, at) : at;   // z in [0,1]
    float z2  = z * z;
    float p   =              -0.0117212f;
    p = fmaf(p, z2,  0.05265332f);
    p = fmaf(p, z2, -0.11643287f);
    p = fmaf(p, z2,  0.19354346f);
    p = fmaf(p, z2, -0.33262347f);
    p = fmaf(p, z2,  0.99997726f);
    p *= z;
    float r = inv ? (CUDART_PIO2_F - p) : p;
    return copysignf(r, t);
}

// one element of masked CIoU; returns masked iou, accumulates loss term
__device__ __forceinline__ float ciou_elem(float4 a, float4 b, float m,
                                           float bn, float& acc) {
    const float EPS   = 1e-9f;
    const float C4PI2 = 4.0f / (CUDART_PI_F * CUDART_PI_F);

    float iw = fmaxf(fminf(a.z, b.z) - fmaxf(a.x, b.x), 0.0f);
    float ih = fmaxf(fminf(a.w, b.w) - fmaxf(a.y, b.y), 0.0f);
    float inter  = iw * ih;
    float wa = a.z - a.x, ha = a.w - a.y;
    float wb = b.z - b.x, hb = b.w - b.y;
    float uni = wa * ha + wb * hb - inter;
    float iou = __fdividef(inter, uni + EPS);

    float cw = fmaxf(a.z, b.z) - fminf(a.x, b.x);
    float ch = fmaxf(a.w, b.w) - fminf(a.y, b.y);
    float c2 = cw * cw + ch * ch + EPS;

    float dx   = (b.x + b.z - a.x - a.z) * 0.5f;
    float dy   = (b.y + b.w - a.y - a.w) * 0.5f;
    float rho2 = dx * dx + dy * dy;

    // atan(wb/(hb+e)) - atan(wa/(ha+e)) == atan(t), single division:
    float hae = ha + EPS, hbe = hb + EPS;
    float t_num = wb * hae - wa * hbe;
    float t_den = fmaf(hbe, hae, wa * wb);
    float t = __fdividef(t_num, t_den);
    float d = fast_atan(t);
    float v = C4PI2 * d * d;
    float av = __fdividef(v * v, 1.0f - iou + v + EPS);   // alpha * v

    float ciou_m = (iou - __fdividef(rho2, c2) - av) * m;
    acc += (1.0f - ciou_m) * bn * m;
    return ciou_m;
}

template <int MODE>
__device__ __forceinline__ float load_mask1(const void* mask, int i) {
    if (MODE == 0)      return ((const float*)mask)[i];
    else if (MODE == 1) return ((const uint8_t*)mask)[i] ? 1.0f : 0.0f;
    else                return ((const int*)mask)[i] ? 1.0f : 0.0f;
}

// Dense loop over output positions j in [1, n]; element e = j-1.
// Stores out[j] are warp-contiguous AND 128B-aligned (j starts at a multiple
// of 32 per lane-0). Input reads at e are 16B-aligned (boxes) / 4B (scalars).
template <int MODE>
__device__ __forceinline__ float mainloop(const float4* __restrict__ pb,
                                          const float4* __restrict__ tb,
                                          const void*   __restrict__ mask,
                                          const float*  __restrict__ box_norm,
                                          float*        __restrict__ out,
                                          int n) {
    float acc = 0.0f;
    const int tid    = blockIdx.x * blockDim.x + threadIdx.x;
    const int stride = gridDim.x * blockDim.x;

    // j runs over output slots: lane0 of warp0 of block0 starts at j=0 (skipped
    // via predicate), so every warp's 32 slots are a 128B-aligned group.
    for (int j = tid; j <= n; j += stride) {
        int e = j - 1;
        if (e >= 0) {
            float4 a  = pb[e];
            float4 b  = tb[e];
            float  bn = box_norm[e];
            float  m  = load_mask1<MODE>(mask, e);
            out[j] = ciou_elem(a, b, m, bn, acc);
        }
    }
    return acc;
}

__global__ void __launch_bounds__(NTHREADS, 4)
ciou_fused_kernel(const float4* __restrict__ pb,
                  const float4* __restrict__ tb,
                  const void*   __restrict__ mask,
                  const float*  __restrict__ box_norm,
                  const float*  __restrict__ cls_norm,
                  float*        __restrict__ out,
                  int n) {
    const int mode = sniff_mask_mode((const uint32_t*)mask);

    float acc;
    if (mode == 0)      acc = mainloop<0>(pb, tb, mask, box_norm, out, n);
    else if (mode == 1) acc = mainloop<1>(pb, tb, mask, box_norm, out, n);
    else                acc = mainloop<2>(pb, tb, mask, box_norm, out, n);

    float bsum = block_reduce_sum(acc);

    __shared__ int s_is_last;
    if (threadIdx.x == 0) {
        g_partials[blockIdx.x] = bsum;
        __threadfence();
        unsigned prev = atomicAdd(&g_ticket, 1u);
        s_is_last = (prev == (unsigned)(gridDim.x - 1));
    }
    __syncthreads();

    if (s_is_last) {
        float v = 0.0f;
        for (int i = threadIdx.x; i < NBLOCKS; i += NTHREADS)
            v += g_partials[i];
        float total = block_reduce_sum(v);
        if (threadIdx.x == 0) {
            out[0] = total / cls_norm[0];
            g_ticket = 0;
        }
    }
}

extern "C" void kernel_launch(void* const* d_in, const int* in_sizes, int n_in,
                              void* d_out, int out_size) {
    const float4*  pb       = (const float4*)d_in[0];
    const float4*  tb       = (const float4*)d_in[1];
    const void*    mask     = d_in[2];
    const float*   box_norm = (const float*)d_in[3];
    const float*   cls_norm = (const float*)d_in[4];
    float*         out      = (float*)d_out;

    int n = in_sizes[2];

    ciou_fused_kernel<<<NBLOCKS, NTHREADS>>>(pb, tb, mask, box_norm,
                                             cls_norm, out, n);
}